// round 17
// baseline (speedup 1.0000x reference)
#include <cuda_runtime.h>
#include <cuda_fp16.h>
#include <cstdint>

#define B_DIM   2048
#define IN_DIM  4096
#define OUT_DIM 4096
#define FAN     64

#define BT        16         // batch rows per block tile (8 half2 pairs)
#define NPAIR     8
#define ROWSTRIDE 4100       // 4B words; 4100 % 32 == 4 -> bank = idx + 4*pair
#define THREADS   1024       // 32 warps
#define OSPLIT    8
#define OCHUNK    (OUT_DIM / OSPLIT)   // 512 outputs per block
#define OPP       128                  // 32 warps * 4 outputs per pass
#define NPASS     (OCHUNK / OPP)       // 4
#define NQUAD     (OUT_DIM / 4)        // 1024

#define FULLMASK 0xffffffffu

// Pack: 4-byte entries (u16 idx | fp16 weight), per quad of outputs {4q..4q+3}:
//   g_pack32[q*256 + f2*8 + g*2 + (t&1)] = entry for step t = 2*f2 + (t&1)
// -> per f2 a warp reads 4 groups x 8B = 32 contiguous bytes; one 128B line
//    serves FOUR f2 steps (4x fewer pack wavefronts than the 8B-entry pack).
__device__ unsigned g_pack32[OUT_DIM * FAN];

// Greedy class schedule, one u32 per (quad, step): byte g = class of group g.
__device__ unsigned g_sched[NQUAD * FAN];

// ---------------------------------------------------------------------------
// dtype sniff helper: JAX may ship int32 despite int64 in the reference.
// For int64 values < 4096 every odd 32-bit word is zero.
// ---------------------------------------------------------------------------
__device__ __forceinline__ unsigned mask_shift(const unsigned* m32) {
    const uint4* p = (const uint4*)m32;
    uint4 a = p[0], b = p[1];
    unsigned odd_or = a.y | a.w | b.y | b.w;
    return (odd_or == 0u) ? 1u : 0u;    // 1 -> int64, 0 -> int32
}

// ---------------------------------------------------------------------------
// Schedule kernel: ONE WARP PER QUAD (1024 warps). Lane-distributed greedy:
// lanes 0..3 are the group agents (holding their group's 4 class counters in
// registers); per step each agent in fixed order 0..3 picks its max-remaining
// class among classes unused this step (fallback: overall max) — the
// validated R10/R12 greedy. Choices are broadcast via shfl; lane 0 stores the
// packed 4-class word. Counts come from lane ballour-free reduction: each
// lane counts 8 entries, 3-round shfl_xor reduce within its 8-lane group.
// ---------------------------------------------------------------------------
__global__ void __launch_bounds__(256) sched_kernel(const unsigned* __restrict__ m32) {
    const int q    = blockIdx.x * (blockDim.x >> 5) + (threadIdx.x >> 5);
    const int lane = threadIdx.x & 31;
    if (q >= NQUAD) return;

    const unsigned sh = mask_shift(m32);

    // count classes: lane = g*8 + s owns entries f = s*8 + k of output q*4+g
    const int g = lane >> 3, s = lane & 7;
    const size_t base = (size_t)(q * 4 + g) * FAN;
    int c0 = 0, c1 = 0, c2 = 0, c3 = 0;
    #pragma unroll
    for (int k = 0; k < 8; k++) {
        unsigned c = m32[(base + s * 8 + k) << sh] & 3u;
        c0 += (c == 0); c1 += (c == 1); c2 += (c == 2); c3 += (c == 3);
    }
    #pragma unroll
    for (int m = 1; m < 8; m <<= 1) {
        c0 += __shfl_xor_sync(FULLMASK, c0, m);
        c1 += __shfl_xor_sync(FULLMASK, c1, m);
        c2 += __shfl_xor_sync(FULLMASK, c2, m);
        c3 += __shfl_xor_sync(FULLMASK, c3, m);
    }
    // agent lane a (0..3) takes the counts of output q*4+a (held in lane a*8)
    const int src = (lane & 3) * 8;
    int r0 = __shfl_sync(FULLMASK, c0, src);
    int r1 = __shfl_sync(FULLMASK, c1, src);
    int r2 = __shfl_sync(FULLMASK, c2, src);
    int r3 = __shfl_sync(FULLMASK, c3, src);

    unsigned* sc = g_sched + (size_t)q * FAN;
    for (int t = 0; t < FAN; t++) {
        int used = 0;
        unsigned word = 0;
        #pragma unroll
        for (int gg = 0; gg < 4; gg++) {
            int pick = 0;
            if (lane == gg) {
                int best = -1, bv = 0;
                if (r0 > 0 && !(used & 1) && r0 > bv) { best = 0; bv = r0; }
                if (r1 > 0 && !(used & 2) && r1 > bv) { best = 1; bv = r1; }
                if (r2 > 0 && !(used & 4) && r2 > bv) { best = 2; bv = r2; }
                if (r3 > 0 && !(used & 8) && r3 > bv) { best = 3; bv = r3; }
                if (best < 0) {
                    if (r0 > bv) { best = 0; bv = r0; }
                    if (r1 > bv) { best = 1; bv = r1; }
                    if (r2 > bv) { best = 2; bv = r2; }
                    if (r3 > bv) { best = 3; bv = r3; }
                }
                r0 -= (best == 0); r1 -= (best == 1);
                r2 -= (best == 2); r3 -= (best == 3);
                pick = best;
            }
            int cls = __shfl_sync(FULLMASK, pick, gg);
            used |= 1 << cls;
            word |= (unsigned)cls << (8 * gg);
        }
        if (lane == 0) sc[t] = word;
    }
}

// ---------------------------------------------------------------------------
// Pack kernel: ONE WARP PER OUTPUT (4096 warps). Validated R13 ballot code
// gives each entry's within-class rank; the schedule scan maps (class, rank)
// -> step t; lanes emit 4-byte (u16 idx | fp16 w) entries straight to pack.
// Pure permutation of each output's 64-term sum (weights fp16-rounded).
// ---------------------------------------------------------------------------
__global__ void __launch_bounds__(256) pack_kernel(const float* __restrict__ w,
                                                   const unsigned* __restrict__ m32) {
    const int o    = blockIdx.x * (blockDim.x >> 5) + (threadIdx.x >> 5);
    const int lane = threadIdx.x & 31;
    if (o >= OUT_DIM) return;
    const int q = o >> 2, g = o & 3;

    const unsigned sh = mask_shift(m32);

    const size_t base = (size_t)o * FAN;
    const unsigned idx0 = m32[(base + lane) << sh];
    const unsigned idx1 = m32[(base + lane + 32) << sh];
    const float    w0   = w[base + lane];
    const float    w1   = w[base + lane + 32];
    const unsigned c0 = idx0 & 3u, c1 = idx1 & 3u;

    unsigned bal0[4], bal1[4];
    #pragma unroll
    for (int c = 0; c < 4; c++) {
        bal0[c] = __ballot_sync(FULLMASK, c0 == (unsigned)c);
        bal1[c] = __ballot_sync(FULLMASK, c1 == (unsigned)c);
    }
    const unsigned lt = (1u << lane) - 1u;

    // within-class ranks (entry1 ranks after all half-0 members of its class)
    const unsigned bA  = (c0 == 0) ? bal0[0] : (c0 == 1) ? bal0[1] : (c0 == 2) ? bal0[2] : bal0[3];
    const int r0c = __popc(bA & lt);
    const unsigned bB0 = (c1 == 0) ? bal0[0] : (c1 == 1) ? bal0[1] : (c1 == 2) ? bal0[2] : bal0[3];
    const unsigned bB1 = (c1 == 0) ? bal1[0] : (c1 == 1) ? bal1[1] : (c1 == 2) ? bal1[2] : bal1[3];
    const int r1c = __popc(bB0) + __popc(bB1 & lt);

    // scan schedule: step of the r-th occurrence of my class for my group
    const unsigned* sc = g_sched + (size_t)q * FAN;
    int t0 = 0, t1 = 0, ka = 0, kb = 0;
    for (int t = 0; t < FAN; t++) {
        unsigned myc = (sc[t] >> (8 * g)) & 0xFFu;
        if (myc == c0) { if (ka == r0c) t0 = t; ka++; }
        if (myc == c1) { if (kb == r1c) t1 = t; kb++; }
    }

    const unsigned e0 = (idx0 & 0xFFFFu) |
        ((unsigned)__half_as_ushort(__float2half_rn(w0)) << 16);
    const unsigned e1 = (idx1 & 0xFFFFu) |
        ((unsigned)__half_as_ushort(__float2half_rn(w1)) << 16);
    const size_t qb = (size_t)q * 256;
    g_pack32[qb + (size_t)((t0 >> 1) * 8 + g * 2 + (t0 & 1))] = e0;
    g_pack32[qb + (size_t)((t1 >> 1) * 8 + g * 2 + (t1 & 1))] = e1;
}

// ---------------------------------------------------------------------------
// Main gather kernel — validated R15 geometry (129.8us), 4B pack entries.
//   smem word (p, idx) = half2( input[brow0+2p][idx], input[brow0+2p+1][idx] )
//   word address = p*4100 + idx  -> bank = idx + 4*p; greedy schedule keeps
//   the 4 groups in distinct mod-4 classes -> near conflict-free LDS.
//   per f2-step: one LDG.64 (32B/warp; one 128B pack line per 4 steps),
//   two LDS.32 half2 gathers, cvt, 4 fp32 FMAs. fp32 accumulation and bias.
// ---------------------------------------------------------------------------
__global__ __launch_bounds__(THREADS, 1)
void gather_kernel(const float* __restrict__ input,
                   const float* __restrict__ bias,
                   float* __restrict__ out) {
    extern __shared__ unsigned tile[];   // NPAIR * ROWSTRIDE words = 131200 B

    const int tid   = threadIdx.x;
    const int wid   = tid >> 5;
    const int lane  = tid & 31;
    const int brow0 = blockIdx.x * BT;
    const int obase = blockIdx.y * OCHUNK;

    // ---- load 16 input rows as 8 half2-pair rows (4 warps per pair)
    {
        const int p = wid >> 2;
        const float4* r0 = (const float4*)(input + (size_t)(brow0 + 2 * p) * IN_DIM);
        const float4* r1 = (const float4*)(input + (size_t)(brow0 + 2 * p + 1) * IN_DIM);
        unsigned* dst = tile + p * ROWSTRIDE;
        #pragma unroll
        for (int j = (wid & 3) * 32 + lane; j < IN_DIM / 4; j += 128) {
            float4 a = r0[j];
            float4 b = r1[j];
            __half2 h0 = __floats2half2_rn(a.x, b.x);
            __half2 h1 = __floats2half2_rn(a.y, b.y);
            __half2 h2 = __floats2half2_rn(a.z, b.z);
            __half2 h3 = __floats2half2_rn(a.w, b.w);
            uint4 hv;
            hv.x = *reinterpret_cast<unsigned*>(&h0);
            hv.y = *reinterpret_cast<unsigned*>(&h1);
            hv.z = *reinterpret_cast<unsigned*>(&h2);
            hv.w = *reinterpret_cast<unsigned*>(&h3);
            *(uint4*)(dst + 4 * j) = hv;   // 16B-aligned: (p*4100 + 4j) % 4 == 0
        }
    }
    __syncthreads();

    const int g  = lane & 3;            // output group within warp (== o & 3)
    const int pr = lane >> 2;           // batch-pair lane
    const unsigned* srow = tile + pr * ROWSTRIDE;

    for (int pass = 0; pass < NPASS; pass++) {
        const int q = (obase >> 2) + pass * (OPP / 4) + wid;   // quad id
        const int o = q * 4 + g;
        const uint2* pk = (const uint2*)(g_pack32 + (size_t)q * 256);

        float x0 = 0.f, x1 = 0.f, y0 = 0.f, y1 = 0.f;
        #pragma unroll 8
        for (int f2 = 0; f2 < FAN / 2; f2++) {
            uint2 v = pk[f2 * 4 + g];             // 8B; 128B line per 4 f2 steps
            unsigned ia = v.x & 0xFFFFu;
            float    wa = __half2float(__ushort_as_half((unsigned short)(v.x >> 16)));
            unsigned ib = v.y & 0xFFFFu;
            float    wb = __half2float(__ushort_as_half((unsigned short)(v.y >> 16)));

            unsigned ua = srow[ia];               // half2: rows (2pr, 2pr+1)
            float2 fa = __half22float2(*reinterpret_cast<const __half2*>(&ua));
            x0 = fmaf(fa.x, wa, x0);
            x1 = fmaf(fa.y, wa, x1);

            unsigned ub = srow[ib];
            float2 fb = __half22float2(*reinterpret_cast<const __half2*>(&ub));
            y0 = fmaf(fb.x, wb, y0);
            y1 = fmaf(fb.y, wb, y1);
        }
        const float bv = bias[o];
        const size_t r0o = (size_t)(brow0 + 2 * pr) * OUT_DIM + o;
        out[r0o]           = x0 + y0 + bv;
        out[r0o + OUT_DIM] = x1 + y1 + bv;
    }
}

// ---------------------------------------------------------------------------
// Harness entry. Inputs (metadata order):
//   0: input            float32 [2048, 4096]
//   1: condensed_weight float32 [4096, 64]
//   2: bias             float32 [4096]
//   3: input_mask       int64-or-int32 [4096, 64]  (detected on device)
// Output: float32 [2048, 4096]
// ---------------------------------------------------------------------------
extern "C" void kernel_launch(void* const* d_in, const int* in_sizes, int n_in,
                              void* d_out, int out_size) {
    const float*    input  = (const float*)d_in[0];
    const float*    weight = (const float*)d_in[1];
    const float*    bias   = (const float*)d_in[2];
    const unsigned* mask32 = (const unsigned*)d_in[3];
    float*          out    = (float*)d_out;
    (void)in_sizes; (void)n_in; (void)out_size;

    sched_kernel<<<NQUAD / 8, 256>>>(mask32);        // 1024 warps (one per quad)
    pack_kernel<<<OUT_DIM / 8, 256>>>(weight, mask32); // 4096 warps (one per output)

    const int smem_bytes = NPAIR * ROWSTRIDE * (int)sizeof(unsigned);   // 131200
    cudaFuncSetAttribute(gather_kernel,
                         cudaFuncAttributeMaxDynamicSharedMemorySize, smem_bytes);

    dim3 grid(B_DIM / BT, OSPLIT);   // (128, 8) = 1024 blocks
    gather_kernel<<<grid, THREADS, smem_bytes>>>(input, bias, out);
}